// round 2
// baseline (speedup 1.0000x reference)
#include <cuda_runtime.h>
#include <cuda_bf16.h>
#include <math.h>

// ---------------------------------------------------------------------------
// FullyConnectedTP: e3nn fully connected tensor product
//  IN  = 64x0e + 32x1o + 16x2e   (dim 240)
//  SH  = 1x0e + 1x1o + 1x2e     (dim 9)
//  OUT = 64x0e + 32x1o + 16x2e  (dim 240)
//  per-edge weights: 13824, N_EDGES = 16384
//
// 11 paths (i1,i2,i3) in instruction order:
//  p0 (0,0,0) p1 (0,1,1) p2 (0,2,2) p3 (1,0,1) p4 (1,1,0) p5 (1,1,2)
//  p6 (1,2,1) p7 (2,0,2) p8 (2,1,1) p9 (2,2,0) p10 (2,2,2)
// ---------------------------------------------------------------------------

#define NPATH 11

__constant__ int C_L1[NPATH]    = {0,0,0,1,1,1,1,2,2,2,2};
__constant__ int C_L2[NPATH]    = {0,1,2,0,1,1,2,0,1,2,2};
__constant__ int C_L3[NPATH]    = {0,1,2,1,0,2,1,2,1,0,2};
// offsets into the packed wigner-3j coefficient array ([i][j][k] per path)
__constant__ int C_COFF[NPATH]  = {0,1,10,35,44,53,98,143,168,213,238};
__constant__ int C_CSZ[NPATH]   = {1,9,25,9,9,45,45,25,45,25,125};
// offsets of D_p[i][k] blocks in shared (total 115)
__constant__ int C_DOFF[NPATH]  = {0,1,4,9,18,21,36,45,70,85,90};
// offsets of tmp_p[u][k] blocks in shared (total 1184)
__constant__ int C_TOFF[NPATH]  = {0,64,256,576,672,704,864,960,1040,1088,1104};
// input-feature offset per path (per i1), sh offset per path (per i2)
__constant__ int C_INOFF[NPATH] = {0,0,0,64,64,64,64,160,160,160,160};
__constant__ int C_SHOFF[NPATH] = {0,1,4,0,1,1,4,0,1,4,4};

// packed normalized real wigner-3j coefficients, computed on-device
__device__ float g_w3j[363];

// ---------------------------------------------------------------------------
// Setup kernel (FP32): computes real e3nn-normalized wigner 3j tensors exactly
// as the reference (SU(2) CG -> complex->real basis change -> Re -> norm 1).
// All magnitudes are small (max factorial 7! = 5040) so FP32 gives ~1e-6
// coefficient accuracy — far inside the 1e-3 gate — at ~100x the FP64 rate.
// ---------------------------------------------------------------------------

__device__ __forceinline__ float d_fact(int n) {
    const float F[9] = {1.f, 1.f, 2.f, 6.f, 24.f, 120.f, 720.f, 5040.f, 40320.f};
    return F[n];
}

__device__ float su2_cg_coeff(int j1, int m1, int j2, int m2, int j3, int m3) {
    if (m3 != m1 + m2) return 0.0f;
    int vmin = -j1 + j2 + m3;
    if (-j1 + m1 > vmin) vmin = -j1 + m1;
    if (0 > vmin) vmin = 0;
    int vmax = j2 + j3 + m1;
    if (j3 - j1 + j2 < vmax) vmax = j3 - j1 + j2;
    if (j3 + m3 < vmax) vmax = j3 + m3;
    float C = sqrtf((float)(2 * j3 + 1)
                    * d_fact(j3 + j1 - j2) * d_fact(j3 - j1 + j2) * d_fact(j1 + j2 - j3)
                    * d_fact(j3 + m3) * d_fact(j3 - m3)
                    / (d_fact(j1 + j2 + j3 + 1) * d_fact(j1 - m1) * d_fact(j1 + m1)
                       * d_fact(j2 - m2) * d_fact(j2 + m2)));
    float S = 0.0f;
    for (int v = vmin; v <= vmax; ++v) {
        float sgn = ((v + j2 + m2) & 1) ? -1.0f : 1.0f;
        S += sgn * d_fact(j2 + j3 + m1 - v) * d_fact(j1 - m1 + v)
             / (d_fact(v) * d_fact(j3 - j1 + j2 - v) * d_fact(j3 + m3 - v)
                * d_fact(v + j1 - j2 - m3));
    }
    return C * S;
}

// entry [r][c] of the real->complex change-of-basis matrix for given l
__device__ void q_entry(int l, int r, int c, float& qre, float& qim) {
    const float s = 0.70710678118654752440f;
    float re = 0.0f, im = 0.0f;
    int m = r - l;
    if (m < 0) {
        if (c == l - m)      re = s;    // col = l + |m|
        else if (c == l + m) im = -s;   // col = l - |m|
    } else if (m == 0) {
        if (c == l) re = 1.0f;
    } else {
        float sg = (m & 1) ? -1.0f : 1.0f;
        if (c == l + m)      re = sg * s;
        else if (c == l - m) im = sg * s;
    }
    // multiply by (-i)^l
    float ore, oim;
    switch (l & 3) {
        case 0: ore =  re; oim =  im; break;
        case 1: ore =  im; oim = -re; break;
        case 2: ore = -re; oim = -im; break;
        default: ore = -im; oim =  re; break;
    }
    qre = ore; qim = oim;
}

__global__ void w3j_setup_kernel() {
    __shared__ float sC[363];
    __shared__ float sInv[NPATH];
    int e = threadIdx.x;

    if (e < 363) {
        int p = 0;
        while (p < NPATH - 1 && e >= C_COFF[p + 1]) ++p;
        int local = e - C_COFF[p];
        int l1 = C_L1[p], l2 = C_L2[p], l3 = C_L3[p];
        int d2 = 2 * l2 + 1, d3 = 2 * l3 + 1;
        int a = local / (d2 * d3);
        int rem = local - a * (d2 * d3);
        int b = rem / d3;
        int c = rem - b * d3;
        // C[a,b,c] = Re sum_{i,k,n} Q1[i,a] Q2[k,b] conj(Q3[c,n]) cg[i,k,n]
        float acc = 0.0f;
        for (int i = 0; i <= 2 * l1; ++i) {
            for (int k = 0; k <= 2 * l2; ++k) {
                int m1 = i - l1, m2 = k - l2, m3 = m1 + m2;
                if (m3 < -l3 || m3 > l3) continue;
                int n = l3 + m3;
                float cg = su2_cg_coeff(l1, m1, l2, m2, l3, m3);
                if (cg == 0.0f) continue;
                float q1r, q1i, q2r, q2i, q3r, q3i;
                q_entry(l1, i, a, q1r, q1i);
                q_entry(l2, k, b, q2r, q2i);
                q_entry(l3, c, n, q3r, q3i);
                q3i = -q3i;  // conj
                float tr = q1r * q2r - q1i * q2i;
                float ti = q1r * q2i + q1i * q2r;
                float ur = tr * q3r - ti * q3i;
                acc += ur * cg;
            }
        }
        sC[e] = acc;
    }
    __syncthreads();
    if (e < NPATH) {
        float ss = 0.f;
        int base = C_COFF[e], sz = C_CSZ[e];
        for (int q = 0; q < sz; ++q) ss += sC[base + q] * sC[base + q];
        sInv[e] = rsqrtf(ss);
    }
    __syncthreads();
    if (e < 363) {
        int p = 0;
        while (p < NPATH - 1 && e >= C_COFF[p + 1]) ++p;
        g_w3j[e] = sC[e] * sInv[p];
    }
}

// ---------------------------------------------------------------------------
// Main kernel: one block per edge, 256 threads.
//   Phase 1: load u(240), v(9) to shared
//   Phase 2: D_p[i][k] = sum_j C_p[i][j][k] * v[j]            (115 elems)
//   Phase 3: tmp_p[u][k] = sum_i u1[u][i] * D_p[i][k]          (1184 elems)
//   Phase 4: out[w3,k] = pw * sum_paths sum_u W_p[u,w3]*tmp_p[u][k]
//            thread t owns output element t (240 active threads)
//   Weight reads are fully coalesced per warp (each u-iteration touches one
//   contiguous 64/128B region; the (2l3+1)-fold redundancy in l=1/l=2 regions
//   is intra-warp broadcast + L1 hits, not extra DRAM traffic).
// ---------------------------------------------------------------------------

// pw = sqrt((2*l3+1)/fan[i3]); fan = {112, 144, 128}
#define PW0 0.09449111825230679f
#define PW1 0.14433756729740643f
#define PW2 0.19764235376052372f

__global__ __launch_bounds__(256) void tp_main_kernel(
    const float* __restrict__ U, const float* __restrict__ V,
    const float* __restrict__ W, float* __restrict__ O)
{
    __shared__ float s_u[240];
    __shared__ float s_v[9];
    __shared__ float s_D[115];
    __shared__ float s_tmp[1184];

    const int z = blockIdx.x;
    const int t = threadIdx.x;
    const float* __restrict__ wrow = W + (size_t)z * 13824;

    if (t < 240) s_u[t] = U[(size_t)z * 240 + t];
    if (t >= 240 && t < 249) s_v[t - 240] = V[(size_t)z * 9 + (t - 240)];
    __syncthreads();

    // Phase 2: D
    if (t < 115) {
        int p = 0;
        while (p < NPATH - 1 && t >= C_DOFF[p + 1]) ++p;
        int local = t - C_DOFF[p];
        int d2 = 2 * C_L2[p] + 1, d3 = 2 * C_L3[p] + 1;
        int i = local / d3;
        int k = local - i * d3;
        const float* Cp = g_w3j + C_COFF[p];
        const float* vp = s_v + C_SHOFF[p];
        float acc = 0.f;
        for (int j = 0; j < d2; ++j)
            acc += Cp[(i * d2 + j) * d3 + k] * vp[j];
        s_D[t] = acc;
    }
    __syncthreads();

    // Phase 3: tmp
    for (int e = t; e < 1184; e += 256) {
        int p = 0;
        while (p < NPATH - 1 && e >= C_TOFF[p + 1]) ++p;
        int local = e - C_TOFF[p];
        int d1 = 2 * C_L1[p] + 1, d3 = 2 * C_L3[p] + 1;
        int u = local / d3;
        int k = local - u * d3;
        const float* up = s_u + C_INOFF[p] + u * d1;
        const float* Dp = s_D + C_DOFF[p];
        float acc = 0.f;
        for (int i = 0; i < d1; ++i)
            acc += up[i] * Dp[i * d3 + k];
        s_tmp[e] = acc;
    }
    __syncthreads();

    // Phase 4: output contraction (streaming weight reads)
    if (t < 240) {
        float acc = 0.f;
        if (t < 64) {
            // out irrep 0 (scalars): w3 = t; paths p0(u<64), p4(u<32), p9(u<16)
            const int w3 = t;
            #pragma unroll 16
            for (int u = 0; u < 64; ++u) acc += wrow[        u * 64 + w3] * s_tmp[       u];
            #pragma unroll 16
            for (int u = 0; u < 32; ++u) acc += wrow[ 8192 + u * 64 + w3] * s_tmp[ 672 + u];
            #pragma unroll 16
            for (int u = 0; u < 16; ++u) acc += wrow[12544 + u * 64 + w3] * s_tmp[1088 + u];
            acc *= PW0;
        } else if (t < 160) {
            // out irrep 1 (l=1): idx = t-64; paths p1(64), p3(32), p6(32), p8(16)
            const int idx = t - 64;
            const int w3 = idx / 3;
            const int k  = idx - w3 * 3;
            #pragma unroll 16
            for (int u = 0; u < 64; ++u) acc += wrow[ 4096 + u * 32 + w3] * s_tmp[  64 + u * 3 + k];
            #pragma unroll 16
            for (int u = 0; u < 32; ++u) acc += wrow[ 7168 + u * 32 + w3] * s_tmp[ 576 + u * 3 + k];
            #pragma unroll 16
            for (int u = 0; u < 32; ++u) acc += wrow[10752 + u * 32 + w3] * s_tmp[ 864 + u * 3 + k];
            #pragma unroll 16
            for (int u = 0; u < 16; ++u) acc += wrow[12032 + u * 32 + w3] * s_tmp[1040 + u * 3 + k];
            acc *= PW1;
        } else {
            // out irrep 2 (l=2): idx = t-160; paths p2(64), p5(32), p7(16), p10(16)
            const int idx = t - 160;
            const int w3 = idx / 5;
            const int k  = idx - w3 * 5;
            #pragma unroll 16
            for (int u = 0; u < 64; ++u) acc += wrow[ 6144 + u * 16 + w3] * s_tmp[ 256 + u * 5 + k];
            #pragma unroll 16
            for (int u = 0; u < 32; ++u) acc += wrow[10240 + u * 16 + w3] * s_tmp[ 704 + u * 5 + k];
            #pragma unroll 16
            for (int u = 0; u < 16; ++u) acc += wrow[11776 + u * 16 + w3] * s_tmp[ 960 + u * 5 + k];
            #pragma unroll 16
            for (int u = 0; u < 16; ++u) acc += wrow[13568 + u * 16 + w3] * s_tmp[1104 + u * 5 + k];
            acc *= PW2;
        }
        O[(size_t)z * 240 + t] = acc;
    }
}

// ---------------------------------------------------------------------------

extern "C" void kernel_launch(void* const* d_in, const int* in_sizes, int n_in,
                              void* d_out, int out_size) {
    const float* u = (const float*)d_in[0];
    const float* v = (const float*)d_in[1];
    const float* w = (const float*)d_in[2];
    float* out = (float*)d_out;

    const int n_edges = in_sizes[0] / 240;

    w3j_setup_kernel<<<1, 384>>>();
    tp_main_kernel<<<n_edges, 256>>>(u, v, w, out);
    (void)n_in; (void)out_size;
}

// round 3
// speedup vs baseline: 1.0574x; 1.0574x over previous
#include <cuda_runtime.h>
#include <cuda_bf16.h>
#include <math.h>

// ---------------------------------------------------------------------------
// FullyConnectedTP: e3nn fully connected tensor product
//  IN  = 64x0e + 32x1o + 16x2e   (dim 240)
//  SH  = 1x0e + 1x1o + 1x2e     (dim 9)
//  OUT = 64x0e + 32x1o + 16x2e  (dim 240)
//  per-edge weights: 13824, N_EDGES = 16384
//
// 11 paths (i1,i2,i3) in instruction order:
//  p0 (0,0,0) p1 (0,1,1) p2 (0,2,2) p3 (1,0,1) p4 (1,1,0) p5 (1,1,2)
//  p6 (1,2,1) p7 (2,0,2) p8 (2,1,1) p9 (2,2,0) p10 (2,2,2)
// ---------------------------------------------------------------------------

#define NPATH 11

__constant__ int C_L1[NPATH]    = {0,0,0,1,1,1,1,2,2,2,2};
__constant__ int C_L2[NPATH]    = {0,1,2,0,1,1,2,0,1,2,2};
__constant__ int C_L3[NPATH]    = {0,1,2,1,0,2,1,2,1,0,2};
__constant__ int C_COFF[NPATH]  = {0,1,10,35,44,53,98,143,168,213,238};
__constant__ int C_CSZ[NPATH]   = {1,9,25,9,9,45,45,25,45,25,125};
__constant__ int C_DOFF[NPATH]  = {0,1,4,9,18,21,36,45,70,85,90};
__constant__ int C_TOFF[NPATH]  = {0,64,256,576,672,704,864,960,1040,1088,1104};
__constant__ int C_INOFF[NPATH] = {0,0,0,64,64,64,64,160,160,160,160};
__constant__ int C_SHOFF[NPATH] = {0,1,4,0,1,1,4,0,1,4,4};

__device__ float g_w3j[363];

// ---------------------------------------------------------------------------
// Setup kernel (FP32): real e3nn-normalized wigner 3j, same math as reference.
// ---------------------------------------------------------------------------

__device__ __forceinline__ float d_fact(int n) {
    const float F[9] = {1.f, 1.f, 2.f, 6.f, 24.f, 120.f, 720.f, 5040.f, 40320.f};
    return F[n];
}

__device__ float su2_cg_coeff(int j1, int m1, int j2, int m2, int j3, int m3) {
    if (m3 != m1 + m2) return 0.0f;
    int vmin = -j1 + j2 + m3;
    if (-j1 + m1 > vmin) vmin = -j1 + m1;
    if (0 > vmin) vmin = 0;
    int vmax = j2 + j3 + m1;
    if (j3 - j1 + j2 < vmax) vmax = j3 - j1 + j2;
    if (j3 + m3 < vmax) vmax = j3 + m3;
    float C = sqrtf((float)(2 * j3 + 1)
                    * d_fact(j3 + j1 - j2) * d_fact(j3 - j1 + j2) * d_fact(j1 + j2 - j3)
                    * d_fact(j3 + m3) * d_fact(j3 - m3)
                    / (d_fact(j1 + j2 + j3 + 1) * d_fact(j1 - m1) * d_fact(j1 + m1)
                       * d_fact(j2 - m2) * d_fact(j2 + m2)));
    float S = 0.0f;
    for (int v = vmin; v <= vmax; ++v) {
        float sgn = ((v + j2 + m2) & 1) ? -1.0f : 1.0f;
        S += sgn * d_fact(j2 + j3 + m1 - v) * d_fact(j1 - m1 + v)
             / (d_fact(v) * d_fact(j3 - j1 + j2 - v) * d_fact(j3 + m3 - v)
                * d_fact(v + j1 - j2 - m3));
    }
    return C * S;
}

__device__ void q_entry(int l, int r, int c, float& qre, float& qim) {
    const float s = 0.70710678118654752440f;
    float re = 0.0f, im = 0.0f;
    int m = r - l;
    if (m < 0) {
        if (c == l - m)      re = s;
        else if (c == l + m) im = -s;
    } else if (m == 0) {
        if (c == l) re = 1.0f;
    } else {
        float sg = (m & 1) ? -1.0f : 1.0f;
        if (c == l + m)      re = sg * s;
        else if (c == l - m) im = sg * s;
    }
    float ore, oim;
    switch (l & 3) {
        case 0: ore =  re; oim =  im; break;
        case 1: ore =  im; oim = -re; break;
        case 2: ore = -re; oim = -im; break;
        default: ore = -im; oim =  re; break;
    }
    qre = ore; qim = oim;
}

__global__ void w3j_setup_kernel() {
    __shared__ float sC[363];
    __shared__ float sInv[NPATH];
    int e = threadIdx.x;

    if (e < 363) {
        int p = 0;
        while (p < NPATH - 1 && e >= C_COFF[p + 1]) ++p;
        int local = e - C_COFF[p];
        int l1 = C_L1[p], l2 = C_L2[p], l3 = C_L3[p];
        int d2 = 2 * l2 + 1, d3 = 2 * l3 + 1;
        int a = local / (d2 * d3);
        int rem = local - a * (d2 * d3);
        int b = rem / d3;
        int c = rem - b * d3;
        float acc = 0.0f;
        for (int i = 0; i <= 2 * l1; ++i) {
            for (int k = 0; k <= 2 * l2; ++k) {
                int m1 = i - l1, m2 = k - l2, m3 = m1 + m2;
                if (m3 < -l3 || m3 > l3) continue;
                int n = l3 + m3;
                float cg = su2_cg_coeff(l1, m1, l2, m2, l3, m3);
                if (cg == 0.0f) continue;
                float q1r, q1i, q2r, q2i, q3r, q3i;
                q_entry(l1, i, a, q1r, q1i);
                q_entry(l2, k, b, q2r, q2i);
                q_entry(l3, c, n, q3r, q3i);
                q3i = -q3i;
                float tr = q1r * q2r - q1i * q2i;
                float ti = q1r * q2i + q1i * q2r;
                float ur = tr * q3r - ti * q3i;
                acc += ur * cg;
            }
        }
        sC[e] = acc;
    }
    __syncthreads();
    if (e < NPATH) {
        float ss = 0.f;
        int base = C_COFF[e], sz = C_CSZ[e];
        for (int q = 0; q < sz; ++q) ss += sC[base + q] * sC[base + q];
        sInv[e] = rsqrtf(ss);
    }
    __syncthreads();
    if (e < 363) {
        int p = 0;
        while (p < NPATH - 1 && e >= C_COFF[p + 1]) ++p;
        g_w3j[e] = sC[e] * sInv[p];
    }
}

// ---------------------------------------------------------------------------
// Main kernel. Phase 4 restructured: float4 weight loads (LDG.128), each
// thread owns a (col4-group, row-group) tile; partials reduced via shared.
// ---------------------------------------------------------------------------

#define PW0 0.09449111825230679f
#define PW1 0.14433756729740643f
#define PW2 0.19764235376052372f

__global__ __launch_bounds__(256) void tp_main_kernel(
    const float* __restrict__ U, const float* __restrict__ V,
    const float* __restrict__ W, float* __restrict__ O)
{
    __shared__ float s_u[240];
    __shared__ float s_v[9];
    __shared__ float s_D[115];
    __shared__ float s_tmp[1184];
    __shared__ float s_red[5120];   // reduction scratch (reused per region)

    const int z = blockIdx.x;
    const int t = threadIdx.x;
    const float* __restrict__ wrow = W + (size_t)z * 13824;
    const float4* __restrict__ w4 = (const float4*)wrow;

    if (t < 240) s_u[t] = U[(size_t)z * 240 + t];
    if (t >= 240 && t < 249) s_v[t - 240] = V[(size_t)z * 9 + (t - 240)];
    __syncthreads();

    // Phase 2: D_p[i][k] = sum_j C_p[i][j][k] * v[j]
    if (t < 115) {
        int p = 0;
        while (p < NPATH - 1 && t >= C_DOFF[p + 1]) ++p;
        int local = t - C_DOFF[p];
        int d2 = 2 * C_L2[p] + 1, d3 = 2 * C_L3[p] + 1;
        int i = local / d3;
        int k = local - i * d3;
        const float* Cp = g_w3j + C_COFF[p];
        const float* vp = s_v + C_SHOFF[p];
        float acc = 0.f;
        for (int j = 0; j < d2; ++j)
            acc += Cp[(i * d2 + j) * d3 + k] * vp[j];
        s_D[t] = acc;
    }
    __syncthreads();

    // Phase 3: tmp_p[u][k] = sum_i u1[u][i] * D_p[i][k]
    for (int e = t; e < 1184; e += 256) {
        int p = 0;
        while (p < NPATH - 1 && e >= C_TOFF[p + 1]) ++p;
        int local = e - C_TOFF[p];
        int d1 = 2 * C_L1[p] + 1, d3 = 2 * C_L3[p] + 1;
        int u = local / d3;
        int k = local - u * d3;
        const float* up = s_u + C_INOFF[p] + u * d1;
        const float* Dp = s_D + C_DOFF[p];
        float acc = 0.f;
        for (int i = 0; i < d1; ++i)
            acc += up[i] * Dp[i * d3 + k];
        s_tmp[e] = acc;
    }
    __syncthreads();

    // ------------------ Phase 4: vectorized weight contraction ------------
    // Region A: out irrep0 (w3<64). Rows of 64 floats (16 float4).
    //   p0: w4[u*16+c], tmp[u]      u<64
    //   p4: w4[2048+u*16+c], tmp[672+u]  u<32
    //   p9: w4[3136+u*16+c], tmp[1088+u] u<16
    const int cA = t & 15, rA = t >> 4;      // 16 cols x 16 rows
    float4 aA = make_float4(0.f, 0.f, 0.f, 0.f);
    #pragma unroll
    for (int s = 0; s < 4; ++s) {
        int u = rA + 16 * s;
        float4 w = w4[u * 16 + cA];
        float tv = s_tmp[u];
        aA.x += w.x * tv; aA.y += w.y * tv; aA.z += w.z * tv; aA.w += w.w * tv;
    }
    #pragma unroll
    for (int s = 0; s < 2; ++s) {
        int u = rA + 16 * s;
        float4 w = w4[2048 + u * 16 + cA];
        float tv = s_tmp[672 + u];
        aA.x += w.x * tv; aA.y += w.y * tv; aA.z += w.z * tv; aA.w += w.w * tv;
    }
    {
        int u = rA;
        float4 w = w4[3136 + u * 16 + cA];
        float tv = s_tmp[1088 + u];
        aA.x += w.x * tv; aA.y += w.y * tv; aA.z += w.z * tv; aA.w += w.w * tv;
    }

    // Region B: out irrep1 (w3<32, k<3). Rows of 32 floats (8 float4).
    //   p1: w4[1024+u*8+c], tmp[64+u*3+k]   u<64
    //   p3: w4[1792+u*8+c], tmp[576+u*3+k]  u<32
    //   p6: w4[2688+u*8+c], tmp[864+u*3+k]  u<32
    //   p8: w4[3008+u*8+c], tmp[1040+u*3+k] u<16
    const int cB = t & 7, rB = t >> 3;       // 8 cols x 32 rows
    float4 b0 = make_float4(0.f,0.f,0.f,0.f);
    float4 b1 = make_float4(0.f,0.f,0.f,0.f);
    float4 b2 = make_float4(0.f,0.f,0.f,0.f);
    #pragma unroll
    for (int s = 0; s < 2; ++s) {
        int u = rB + 32 * s;
        float4 w = w4[1024 + u * 8 + cB];
        float t0 = s_tmp[64 + u * 3], t1 = s_tmp[64 + u * 3 + 1], t2 = s_tmp[64 + u * 3 + 2];
        b0.x += w.x*t0; b0.y += w.y*t0; b0.z += w.z*t0; b0.w += w.w*t0;
        b1.x += w.x*t1; b1.y += w.y*t1; b1.z += w.z*t1; b1.w += w.w*t1;
        b2.x += w.x*t2; b2.y += w.y*t2; b2.z += w.z*t2; b2.w += w.w*t2;
    }
    {
        int u = rB;
        float4 w = w4[1792 + u * 8 + cB];
        float t0 = s_tmp[576 + u * 3], t1 = s_tmp[576 + u * 3 + 1], t2 = s_tmp[576 + u * 3 + 2];
        b0.x += w.x*t0; b0.y += w.y*t0; b0.z += w.z*t0; b0.w += w.w*t0;
        b1.x += w.x*t1; b1.y += w.y*t1; b1.z += w.z*t1; b1.w += w.w*t1;
        b2.x += w.x*t2; b2.y += w.y*t2; b2.z += w.z*t2; b2.w += w.w*t2;
    }
    {
        int u = rB;
        float4 w = w4[2688 + u * 8 + cB];
        float t0 = s_tmp[864 + u * 3], t1 = s_tmp[864 + u * 3 + 1], t2 = s_tmp[864 + u * 3 + 2];
        b0.x += w.x*t0; b0.y += w.y*t0; b0.z += w.z*t0; b0.w += w.w*t0;
        b1.x += w.x*t1; b1.y += w.y*t1; b1.z += w.z*t1; b1.w += w.w*t1;
        b2.x += w.x*t2; b2.y += w.y*t2; b2.z += w.z*t2; b2.w += w.w*t2;
    }
    if (rB < 16) {
        int u = rB;
        float4 w = w4[3008 + u * 8 + cB];
        float t0 = s_tmp[1040 + u * 3], t1 = s_tmp[1040 + u * 3 + 1], t2 = s_tmp[1040 + u * 3 + 2];
        b0.x += w.x*t0; b0.y += w.y*t0; b0.z += w.z*t0; b0.w += w.w*t0;
        b1.x += w.x*t1; b1.y += w.y*t1; b1.z += w.z*t1; b1.w += w.w*t1;
        b2.x += w.x*t2; b2.y += w.y*t2; b2.z += w.z*t2; b2.w += w.w*t2;
    }

    // Region C: out irrep2 (w3<16, k<5). Rows of 16 floats (4 float4).
    //   p2:  w4[1536+u*4+c],  tmp[256 +u*5+k] u<64   (row group 0: row=rC)
    //   p5:  w4[2560+u*4+c],  tmp[704 +u*5+k] u<32   (row group 1: rC<32)
    //   p7:  w4[2944+u*4+c],  tmp[960 +u*5+k] u<16   (rC in [32,48))
    //   p10: w4[3392+u*4+c],  tmp[1104+u*5+k] u<16   (rC in [48,64))
    const int cC = t & 3, rC = t >> 2;       // 4 cols x 64 rows
    float4 c0 = make_float4(0.f,0.f,0.f,0.f);
    float4 c1 = make_float4(0.f,0.f,0.f,0.f);
    float4 c2 = make_float4(0.f,0.f,0.f,0.f);
    float4 c3 = make_float4(0.f,0.f,0.f,0.f);
    float4 c4 = make_float4(0.f,0.f,0.f,0.f);
    {
        int u = rC;
        float4 w = w4[1536 + u * 4 + cC];
        const float* tp = s_tmp + 256 + u * 5;
        float t0=tp[0], t1=tp[1], t2=tp[2], t3=tp[3], t4=tp[4];
        c0.x += w.x*t0; c0.y += w.y*t0; c0.z += w.z*t0; c0.w += w.w*t0;
        c1.x += w.x*t1; c1.y += w.y*t1; c1.z += w.z*t1; c1.w += w.w*t1;
        c2.x += w.x*t2; c2.y += w.y*t2; c2.z += w.z*t2; c2.w += w.w*t2;
        c3.x += w.x*t3; c3.y += w.y*t3; c3.z += w.z*t3; c3.w += w.w*t3;
        c4.x += w.x*t4; c4.y += w.y*t4; c4.z += w.z*t4; c4.w += w.w*t4;
    }
    {
        int wbase, tbase, u;
        if (rC < 32)      { u = rC;      wbase = 2560; tbase = 704;  }
        else if (rC < 48) { u = rC - 32; wbase = 2944; tbase = 960;  }
        else              { u = rC - 48; wbase = 3392; tbase = 1104; }
        float4 w = w4[wbase + u * 4 + cC];
        const float* tp = s_tmp + tbase + u * 5;
        float t0=tp[0], t1=tp[1], t2=tp[2], t3=tp[3], t4=tp[4];
        c0.x += w.x*t0; c0.y += w.y*t0; c0.z += w.z*t0; c0.w += w.w*t0;
        c1.x += w.x*t1; c1.y += w.y*t1; c1.z += w.z*t1; c1.w += w.w*t1;
        c2.x += w.x*t2; c2.y += w.y*t2; c2.z += w.z*t2; c2.w += w.w*t2;
        c3.x += w.x*t3; c3.y += w.y*t3; c3.z += w.z*t3; c3.w += w.w*t3;
        c4.x += w.x*t4; c4.y += w.y*t4; c4.z += w.z*t4; c4.w += w.w*t4;
    }

    // ------------------ Reductions (shared memory) ------------------------
    float* outrow = O + (size_t)z * 240;

    // Region A: partial at s_red[(rA*16+cA)*4 + comp] = s_red[rA*64 + w3]
    ((float4*)s_red)[t] = aA;
    __syncthreads();
    if (t < 64) {
        float s = 0.f;
        #pragma unroll
        for (int r = 0; r < 16; ++r) s += s_red[r * 64 + t];
        outrow[t] = PW0 * s;
    }
    __syncthreads();

    // Region B: partial (rB,cB,k,comp) at s_red[(t*3+k)*4+comp]
    {
        float4* rb = ((float4*)s_red) + t * 3;
        rb[0] = b0; rb[1] = b1; rb[2] = b2;
    }
    __syncthreads();
    if (t < 96) {
        int w3 = t / 3, k = t - w3 * 3;
        int c = w3 >> 2, comp = w3 & 3;
        float s = 0.f;
        #pragma unroll
        for (int r = 0; r < 32; ++r) s += s_red[((r * 8 + c) * 3 + k) * 4 + comp];
        outrow[64 + w3 * 3 + k] = PW1 * s;
    }
    __syncthreads();

    // Region C: partial (rC,cC,k,comp) at s_red[(t*5+k)*4+comp]
    {
        float4* rc = ((float4*)s_red) + t * 5;
        rc[0] = c0; rc[1] = c1; rc[2] = c2; rc[3] = c3; rc[4] = c4;
    }
    __syncthreads();
    if (t < 80) {
        int w3 = t / 5, k = t - w3 * 5;
        int c = w3 >> 2, comp = w3 & 3;
        float s = 0.f;
        #pragma unroll
        for (int r = 0; r < 64; ++r) s += s_red[((r * 4 + c) * 5 + k) * 4 + comp];
        outrow[160 + w3 * 5 + k] = PW2 * s;
    }
}

// ---------------------------------------------------------------------------

extern "C" void kernel_launch(void* const* d_in, const int* in_sizes, int n_in,
                              void* d_out, int out_size) {
    const float* u = (const float*)d_in[0];
    const float* v = (const float*)d_in[1];
    const float* w = (const float*)d_in[2];
    float* out = (float*)d_out;

    const int n_edges = in_sizes[0] / 240;

    w3j_setup_kernel<<<1, 384>>>();
    tp_main_kernel<<<n_edges, 256>>>(u, v, w, out);
    (void)n_in; (void)out_size;
}

// round 5
// speedup vs baseline: 1.0654x; 1.0076x over previous
#include <cuda_runtime.h>
#include <cuda_bf16.h>
#include <math.h>

// ---------------------------------------------------------------------------
// FullyConnectedTP: e3nn fully connected tensor product
//  IN  = 64x0e + 32x1o + 16x2e   (dim 240)
//  SH  = 1x0e + 1x1o + 1x2e     (dim 9)
//  OUT = 64x0e + 32x1o + 16x2e  (dim 240)
//  per-edge weights: 13824, N_EDGES = 16384
// ---------------------------------------------------------------------------

#define NPATH 11

__constant__ int C_L1[NPATH]    = {0,0,0,1,1,1,1,2,2,2,2};
__constant__ int C_L2[NPATH]    = {0,1,2,0,1,1,2,0,1,2,2};
__constant__ int C_L3[NPATH]    = {0,1,2,1,0,2,1,2,1,0,2};
__constant__ int C_COFF[NPATH]  = {0,1,10,35,44,53,98,143,168,213,238};
__constant__ int C_CSZ[NPATH]   = {1,9,25,9,9,45,45,25,45,25,125};
__constant__ int C_DOFF[NPATH]  = {0,1,4,9,18,21,36,45,70,85,90};
__constant__ int C_TOFF[NPATH]  = {0,64,256,576,672,704,864,960,1040,1088,1104};
__constant__ int C_INOFF[NPATH] = {0,0,0,64,64,64,64,160,160,160,160};
__constant__ int C_SHOFF[NPATH] = {0,1,4,0,1,1,4,0,1,4,4};

__device__ float    g_w3j[363];
__device__ unsigned g_desc2[115];   // phase-2 element descriptors
__device__ unsigned g_desc3[1184];  // phase-3 element descriptors

// ---------------------------------------------------------------------------
// Setup kernel (FP32): wigner 3j + descriptor tables.
// ---------------------------------------------------------------------------

__device__ __forceinline__ float d_fact(int n) {
    const float F[9] = {1.f, 1.f, 2.f, 6.f, 24.f, 120.f, 720.f, 5040.f, 40320.f};
    return F[n];
}

__device__ float su2_cg_coeff(int j1, int m1, int j2, int m2, int j3, int m3) {
    if (m3 != m1 + m2) return 0.0f;
    int vmin = -j1 + j2 + m3;
    if (-j1 + m1 > vmin) vmin = -j1 + m1;
    if (0 > vmin) vmin = 0;
    int vmax = j2 + j3 + m1;
    if (j3 - j1 + j2 < vmax) vmax = j3 - j1 + j2;
    if (j3 + m3 < vmax) vmax = j3 + m3;
    float C = sqrtf((float)(2 * j3 + 1)
                    * d_fact(j3 + j1 - j2) * d_fact(j3 - j1 + j2) * d_fact(j1 + j2 - j3)
                    * d_fact(j3 + m3) * d_fact(j3 - m3)
                    / (d_fact(j1 + j2 + j3 + 1) * d_fact(j1 - m1) * d_fact(j1 + m1)
                       * d_fact(j2 - m2) * d_fact(j2 + m2)));
    float S = 0.0f;
    for (int v = vmin; v <= vmax; ++v) {
        float sgn = ((v + j2 + m2) & 1) ? -1.0f : 1.0f;
        S += sgn * d_fact(j2 + j3 + m1 - v) * d_fact(j1 - m1 + v)
             / (d_fact(v) * d_fact(j3 - j1 + j2 - v) * d_fact(j3 + m3 - v)
                * d_fact(v + j1 - j2 - m3));
    }
    return C * S;
}

__device__ void q_entry(int l, int r, int c, float& qre, float& qim) {
    const float s = 0.70710678118654752440f;
    float re = 0.0f, im = 0.0f;
    int m = r - l;
    if (m < 0) {
        if (c == l - m)      re = s;
        else if (c == l + m) im = -s;
    } else if (m == 0) {
        if (c == l) re = 1.0f;
    } else {
        float sg = (m & 1) ? -1.0f : 1.0f;
        if (c == l + m)      re = sg * s;
        else if (c == l - m) im = sg * s;
    }
    float ore, oim;
    switch (l & 3) {
        case 0: ore =  re; oim =  im; break;
        case 1: ore =  im; oim = -re; break;
        case 2: ore = -re; oim = -im; break;
        default: ore = -im; oim =  re; break;
    }
    qre = ore; qim = oim;
}

__global__ void w3j_setup_kernel() {
    __shared__ float sC[363];
    __shared__ float sInv[NPATH];
    int e = threadIdx.x;

    if (e < 363) {
        int p = 0;
        while (p < NPATH - 1 && e >= C_COFF[p + 1]) ++p;
        int local = e - C_COFF[p];
        int l1 = C_L1[p], l2 = C_L2[p], l3 = C_L3[p];
        int d2 = 2 * l2 + 1, d3 = 2 * l3 + 1;
        int a = local / (d2 * d3);
        int rem = local - a * (d2 * d3);
        int b = rem / d3;
        int c = rem - b * d3;
        float acc = 0.0f;
        for (int i = 0; i <= 2 * l1; ++i) {
            for (int k = 0; k <= 2 * l2; ++k) {
                int m1 = i - l1, m2 = k - l2, m3 = m1 + m2;
                if (m3 < -l3 || m3 > l3) continue;
                int n = l3 + m3;
                float cg = su2_cg_coeff(l1, m1, l2, m2, l3, m3);
                if (cg == 0.0f) continue;
                float q1r, q1i, q2r, q2i, q3r, q3i;
                q_entry(l1, i, a, q1r, q1i);
                q_entry(l2, k, b, q2r, q2i);
                q_entry(l3, c, n, q3r, q3i);
                q3i = -q3i;
                float tr = q1r * q2r - q1i * q2i;
                float ti = q1r * q2i + q1i * q2r;
                float ur = tr * q3r - ti * q3i;
                acc += ur * cg;
            }
        }
        sC[e] = acc;
    }
    __syncthreads();
    if (e < NPATH) {
        float ss = 0.f;
        int base = C_COFF[e], sz = C_CSZ[e];
        for (int q = 0; q < sz; ++q) ss += sC[base + q] * sC[base + q];
        sInv[e] = rsqrtf(ss);
    }
    __syncthreads();
    if (e < 363) {
        int p = 0;
        while (p < NPATH - 1 && e >= C_COFF[p + 1]) ++p;
        g_w3j[e] = sC[e] * sInv[p];
    }

    // descriptor table for phase 2 (115 elements)
    if (e < 115) {
        int p = 0;
        while (p < NPATH - 1 && e >= C_DOFF[p + 1]) ++p;
        int local = e - C_DOFF[p];
        int d2 = 2 * C_L2[p] + 1, d3 = 2 * C_L3[p] + 1;
        int i = local / d3;
        int k = local - i * d3;
        unsigned base = C_COFF[p] + (i * d2) * d3 + k;   // < 363
        g_desc2[e] = base | ((unsigned)d3 << 10) | ((unsigned)d2 << 13)
                   | ((unsigned)C_SHOFF[p] << 16);
    }
    // descriptor table for phase 3 (1184 elements)
    for (int e3 = e; e3 < 1184; e3 += blockDim.x) {
        int p = 0;
        while (p < NPATH - 1 && e3 >= C_TOFF[p + 1]) ++p;
        int local = e3 - C_TOFF[p];
        int d1 = 2 * C_L1[p] + 1, d3 = 2 * C_L3[p] + 1;
        int u = local / d3;
        int k = local - u * d3;
        unsigned su = C_INOFF[p] + u * d1;   // < 240
        unsigned dk = C_DOFF[p] + k;         // < 115
        g_desc3[e3] = su | (dk << 8) | ((unsigned)d3 << 15) | ((unsigned)d1 << 18);
    }
}

// ---------------------------------------------------------------------------
// Main kernel: weights prefetched into registers FIRST (before barriers), so
// each block's 55KB DRAM burst overlaps its own phase-2/3 compute.
// ---------------------------------------------------------------------------

#define PW0 0.09449111825230679f
#define PW1 0.14433756729740643f
#define PW2 0.19764235376052372f

__global__ __launch_bounds__(256, 2) void tp_main_kernel(
    const float* __restrict__ U, const float* __restrict__ V,
    const float* __restrict__ W, float* __restrict__ O)
{
    __shared__ float s_u[240];
    __shared__ float s_v[9];
    __shared__ float s_D[115];
    __shared__ float s_tmp[1184];
    __shared__ float s_red[5120];

    const int z = blockIdx.x;
    const int t = threadIdx.x;
    const float4* __restrict__ w4 = (const float4*)(W + (size_t)z * 13824);

    // ---- Phase 1: input staging -----------------------------------------
    if (t < 240) s_u[t] = U[(size_t)z * 240 + t];
    if (t >= 240 && t < 249) s_v[t - 240] = V[(size_t)z * 9 + (t - 240)];

    // ---- Weight prefetch (issued before any barrier) --------------------
    const int cA = t & 15, rA = t >> 4;      // region A: 16 cols x 16 rows
    const int cB = t & 7,  rB = t >> 3;      // region B: 8 cols x 32 rows
    const int cC = t & 3,  rC = t >> 2;      // region C: 4 cols x 64 rows

    float4 wA0 = w4[(rA     ) * 16 + cA];
    float4 wA1 = w4[(rA + 16) * 16 + cA];
    float4 wA2 = w4[(rA + 32) * 16 + cA];
    float4 wA3 = w4[(rA + 48) * 16 + cA];
    float4 wA4 = w4[2048 + (rA     ) * 16 + cA];
    float4 wA5 = w4[2048 + (rA + 16) * 16 + cA];
    float4 wA6 = w4[3136 + rA * 16 + cA];

    float4 wB0 = w4[1024 + (rB     ) * 8 + cB];
    float4 wB1 = w4[1024 + (rB + 32) * 8 + cB];
    float4 wB2 = w4[1792 + rB * 8 + cB];
    float4 wB3 = w4[2688 + rB * 8 + cB];
    float4 wB4 = (rB < 16) ? w4[3008 + rB * 8 + cB] : make_float4(0.f,0.f,0.f,0.f);

    float4 wC0 = w4[1536 + rC * 4 + cC];
    int wbaseC, tbaseC, uC;
    if (rC < 32)      { uC = rC;      wbaseC = 2560; tbaseC = 704;  }
    else if (rC < 48) { uC = rC - 32; wbaseC = 2944; tbaseC = 960;  }
    else              { uC = rC - 48; wbaseC = 3392; tbaseC = 1104; }
    float4 wC1 = w4[wbaseC + uC * 4 + cC];

    __syncthreads();

    // ---- Phase 2: D (table-driven) --------------------------------------
    if (t < 115) {
        unsigned d  = g_desc2[t];
        int base = d & 1023;
        int d3   = (d >> 10) & 7;
        int d2   = (d >> 13) & 7;
        int sh   = (d >> 16) & 15;
        float acc = 0.f;
        for (int j = 0; j < d2; ++j)
            acc += g_w3j[base + j * d3] * s_v[sh + j];
        s_D[t] = acc;
    }
    __syncthreads();

    // ---- Phase 3: tmp (table-driven) ------------------------------------
    #pragma unroll
    for (int jj = 0; jj < 5; ++jj) {
        int e = t + 256 * jj;
        if (e < 1184) {
            unsigned d = g_desc3[e];
            int su = d & 255;
            int dk = (d >> 8) & 127;
            int d3 = (d >> 15) & 7;
            int d1 = (d >> 18) & 7;
            float acc = 0.f;
            for (int i = 0; i < d1; ++i)
                acc += s_u[su + i] * s_D[dk + i * d3];
            s_tmp[e] = acc;
        }
    }
    __syncthreads();

    // ---- Phase 4: FMAs with prefetched weights ---------------------------
    float4 aA = make_float4(0.f,0.f,0.f,0.f);
    {
        float tv;
        tv = s_tmp[rA];          aA.x += wA0.x*tv; aA.y += wA0.y*tv; aA.z += wA0.z*tv; aA.w += wA0.w*tv;
        tv = s_tmp[rA + 16];     aA.x += wA1.x*tv; aA.y += wA1.y*tv; aA.z += wA1.z*tv; aA.w += wA1.w*tv;
        tv = s_tmp[rA + 32];     aA.x += wA2.x*tv; aA.y += wA2.y*tv; aA.z += wA2.z*tv; aA.w += wA2.w*tv;
        tv = s_tmp[rA + 48];     aA.x += wA3.x*tv; aA.y += wA3.y*tv; aA.z += wA3.z*tv; aA.w += wA3.w*tv;
        tv = s_tmp[672 + rA];    aA.x += wA4.x*tv; aA.y += wA4.y*tv; aA.z += wA4.z*tv; aA.w += wA4.w*tv;
        tv = s_tmp[672 + rA+16]; aA.x += wA5.x*tv; aA.y += wA5.y*tv; aA.z += wA5.z*tv; aA.w += wA5.w*tv;
        tv = s_tmp[1088 + rA];   aA.x += wA6.x*tv; aA.y += wA6.y*tv; aA.z += wA6.z*tv; aA.w += wA6.w*tv;
    }

    float4 b0 = make_float4(0.f,0.f,0.f,0.f);
    float4 b1 = make_float4(0.f,0.f,0.f,0.f);
    float4 b2 = make_float4(0.f,0.f,0.f,0.f);
    {
        const float* tp;
        tp = s_tmp + 64 + rB * 3;
        b0.x += wB0.x*tp[0]; b0.y += wB0.y*tp[0]; b0.z += wB0.z*tp[0]; b0.w += wB0.w*tp[0];
        b1.x += wB0.x*tp[1]; b1.y += wB0.y*tp[1]; b1.z += wB0.z*tp[1]; b1.w += wB0.w*tp[1];
        b2.x += wB0.x*tp[2]; b2.y += wB0.y*tp[2]; b2.z += wB0.z*tp[2]; b2.w += wB0.w*tp[2];
        tp = s_tmp + 64 + (rB + 32) * 3;
        b0.x += wB1.x*tp[0]; b0.y += wB1.y*tp[0]; b0.z += wB1.z*tp[0]; b0.w += wB1.w*tp[0];
        b1.x += wB1.x*tp[1]; b1.y += wB1.y*tp[1]; b1.z += wB1.z*tp[1]; b1.w += wB1.w*tp[1];
        b2.x += wB1.x*tp[2]; b2.y += wB1.y*tp[2]; b2.z += wB1.z*tp[2]; b2.w += wB1.w*tp[2];
        tp = s_tmp + 576 + rB * 3;
        b0.x += wB2.x*tp[0]; b0.y += wB2.y*tp[0]; b0.z += wB2.z*tp[0]; b0.w += wB2.w*tp[0];
        b1.x += wB2.x*tp[1]; b1.y += wB2.y*tp[1]; b1.z += wB2.z*tp[1]; b1.w += wB2.w*tp[1];
        b2.x += wB2.x*tp[2]; b2.y += wB2.y*tp[2]; b2.z += wB2.z*tp[2]; b2.w += wB2.w*tp[2];
        tp = s_tmp + 864 + rB * 3;
        b0.x += wB3.x*tp[0]; b0.y += wB3.y*tp[0]; b0.z += wB3.z*tp[0]; b0.w += wB3.w*tp[0];
        b1.x += wB3.x*tp[1]; b1.y += wB3.y*tp[1]; b1.z += wB3.z*tp[1]; b1.w += wB3.w*tp[1];
        b2.x += wB3.x*tp[2]; b2.y += wB3.y*tp[2]; b2.z += wB3.z*tp[2]; b2.w += wB3.w*tp[2];
        if (rB < 16) {
            tp = s_tmp + 1040 + rB * 3;
            b0.x += wB4.x*tp[0]; b0.y += wB4.y*tp[0]; b0.z += wB4.z*tp[0]; b0.w += wB4.w*tp[0];
            b1.x += wB4.x*tp[1]; b1.y += wB4.y*tp[1]; b1.z += wB4.z*tp[1]; b1.w += wB4.w*tp[1];
            b2.x += wB4.x*tp[2]; b2.y += wB4.y*tp[2]; b2.z += wB4.z*tp[2]; b2.w += wB4.w*tp[2];
        }
    }

    float4 c0 = make_float4(0.f,0.f,0.f,0.f);
    float4 c1 = make_float4(0.f,0.f,0.f,0.f);
    float4 c2 = make_float4(0.f,0.f,0.f,0.f);
    float4 c3 = make_float4(0.f,0.f,0.f,0.f);
    float4 c4 = make_float4(0.f,0.f,0.f,0.f);
    {
        const float* tp = s_tmp + 256 + rC * 5;
        float t0=tp[0], t1=tp[1], t2=tp[2], t3=tp[3], t4=tp[4];
        c0.x += wC0.x*t0; c0.y += wC0.y*t0; c0.z += wC0.z*t0; c0.w += wC0.w*t0;
        c1.x += wC0.x*t1; c1.y += wC0.y*t1; c1.z += wC0.z*t1; c1.w += wC0.w*t1;
        c2.x += wC0.x*t2; c2.y += wC0.y*t2; c2.z += wC0.z*t2; c2.w += wC0.w*t2;
        c3.x += wC0.x*t3; c3.y += wC0.y*t3; c3.z += wC0.z*t3; c3.w += wC0.w*t3;
        c4.x += wC0.x*t4; c4.y += wC0.y*t4; c4.z += wC0.z*t4; c4.w += wC0.w*t4;
        tp = s_tmp + tbaseC + uC * 5;
        t0=tp[0]; t1=tp[1]; t2=tp[2]; t3=tp[3]; t4=tp[4];
        c0.x += wC1.x*t0; c0.y += wC1.y*t0; c0.z += wC1.z*t0; c0.w += wC1.w*t0;
        c1.x += wC1.x*t1; c1.y += wC1.y*t1; c1.z += wC1.z*t1; c1.w += wC1.w*t1;
        c2.x += wC1.x*t2; c2.y += wC1.y*t2; c2.z += wC1.z*t2; c2.w += wC1.w*t2;
        c3.x += wC1.x*t3; c3.y += wC1.y*t3; c3.z += wC1.z*t3; c3.w += wC1.w*t3;
        c4.x += wC1.x*t4; c4.y += wC1.y*t4; c4.z += wC1.z*t4; c4.w += wC1.w*t4;
    }

    // ---- Reductions ------------------------------------------------------
    float* outrow = O + (size_t)z * 240;

    ((float4*)s_red)[t] = aA;
    __syncthreads();
    if (t < 64) {
        float s = 0.f;
        #pragma unroll
        for (int r = 0; r < 16; ++r) s += s_red[r * 64 + t];
        outrow[t] = PW0 * s;
    }
    __syncthreads();

    {
        float4* rb = ((float4*)s_red) + t * 3;
        rb[0] = b0; rb[1] = b1; rb[2] = b2;
    }
    __syncthreads();
    if (t < 96) {
        int w3 = t / 3, k = t - w3 * 3;
        int c = w3 >> 2, comp = w3 & 3;
        float s = 0.f;
        #pragma unroll
        for (int r = 0; r < 32; ++r) s += s_red[((r * 8 + c) * 3 + k) * 4 + comp];
        outrow[64 + w3 * 3 + k] = PW1 * s;
    }
    __syncthreads();

    {
        float4* rc = ((float4*)s_red) + t * 5;
        rc[0] = c0; rc[1] = c1; rc[2] = c2; rc[3] = c3; rc[4] = c4;
    }
    __syncthreads();
    if (t < 80) {
        int w3 = t / 5, k = t - w3 * 5;
        int c = w3 >> 2, comp = w3 & 3;
        float s = 0.f;
        #pragma unroll
        for (int r = 0; r < 64; ++r) s += s_red[((r * 4 + c) * 5 + k) * 4 + comp];
        outrow[160 + w3 * 5 + k] = PW2 * s;
    }
}

// ---------------------------------------------------------------------------

extern "C" void kernel_launch(void* const* d_in, const int* in_sizes, int n_in,
                              void* d_out, int out_size) {
    const float* u = (const float*)d_in[0];
    const float* v = (const float*)d_in[1];
    const float* w = (const float*)d_in[2];
    float* out = (float*)d_out;

    const int n_edges = in_sizes[0] / 240;

    w3j_setup_kernel<<<1, 384>>>();
    tp_main_kernel<<<n_edges, 256>>>(u, v, w, out);
    (void)n_in; (void)out_size;
}